// round 9
// baseline (speedup 1.0000x reference)
#include <cuda_runtime.h>
#include <cstdint>

#define NB 4
#define NN 4096
#define ND 32
#define NC 256
#define BM 64
#define BN 32
#define NT (NN/BN)

// ---------------- scratch (device globals; allocation-free rule) -----------
// g as bf16 hi/lo pairs, row-major: u32[row][16], u32 j = (g[row][2j], g[row][2j+1])
__device__ uint32_t d_gbh[NB*NN*16];
__device__ uint32_t d_gbl[NB*NN*16];
// f^T B-fragments: uint2[b][key][8]; entry e=(ks*4+tq):
//   .x = pack(f[key][16ks+2tq], f[key][16ks+2tq+1])   (b0: k-rows 2tq,2tq+1)
//   .y = pack(f[key][16ks+2tq+8], f[key][16ks+2tq+9]) (b1: k-rows +8)
__device__ uint2 d_fqh[NB*NN*8];
__device__ uint2 d_fql[NB*NN*8];
// h quads (tf32): [b][kp][q] = (h[k1][c], h[k1+4][c], h[k1][c+32], h[k1+4][c+32])
//   kp = (k1>>3)*4 + (k1&3);  q = (c>>6)*32 + (c&31)  (c&63<32)
__device__ float4 d_hq[NB*2048*128];

// ---------------- helpers ---------------------------------------------------
__device__ __forceinline__ uint32_t smem_u32(const void* p) {
    return (uint32_t)__cvta_generic_to_shared(p);
}
__device__ __forceinline__ void cpa16(uint32_t dst, const void* src) {
    asm volatile("cp.async.cg.shared.global [%0], [%1], 16;" :: "r"(dst), "l"(src));
}
__device__ __forceinline__ void cpa_commit() {
    asm volatile("cp.async.commit_group;" ::: "memory");
}
template<int N> __device__ __forceinline__ void cpa_wait() {
    asm volatile("cp.async.wait_group %0;" :: "n"(N) : "memory");
}
__device__ __forceinline__ void barx(int id, int cnt) {
    asm volatile("bar.sync %0, %1;" :: "r"(id), "r"(cnt) : "memory");
}
__device__ __forceinline__ float tf32r(float v) {
    uint32_t r;
    asm("cvt.rna.tf32.f32 %0, %1;" : "=r"(r) : "f"(v));
    return __uint_as_float(r);
}
// bf16x2 pack: low half = lo element, high half = hi element
__device__ __forceinline__ uint32_t packbf(float lo, float hi) {
    uint32_t r;
    asm("cvt.rn.bf16x2.f32 %0, %1, %2;" : "=r"(r) : "f"(hi), "f"(lo));
    return r;
}
__device__ __forceinline__ float bf_lo(uint32_t p) { return __uint_as_float(p << 16); }
__device__ __forceinline__ float bf_hi(uint32_t p) { return __uint_as_float(p & 0xffff0000u); }

// tf32 m16n8k8 (PV)
__device__ __forceinline__ void mma8(float* c, const uint32_t* a, float b0, float b1) {
    asm volatile("mma.sync.aligned.m16n8k8.row.col.f32.tf32.tf32.f32 "
        "{%0,%1,%2,%3}, {%4,%5,%6,%7}, {%8,%9}, {%0,%1,%2,%3};"
        : "+f"(c[0]), "+f"(c[1]), "+f"(c[2]), "+f"(c[3])
        : "r"(a[0]), "r"(a[1]), "r"(a[2]), "r"(a[3]),
          "r"(__float_as_uint(b0)), "r"(__float_as_uint(b1)));
}
// bf16 m16n8k16 (QK)
__device__ __forceinline__ void mma16(float* c, const uint32_t* a, uint32_t b0, uint32_t b1) {
    asm volatile("mma.sync.aligned.m16n8k16.row.col.f32.bf16.bf16.f32 "
        "{%0,%1,%2,%3}, {%4,%5,%6,%7}, {%8,%9}, {%0,%1,%2,%3};"
        : "+f"(c[0]), "+f"(c[1]), "+f"(c[2]), "+f"(c[3])
        : "r"(a[0]), "r"(a[1]), "r"(a[2]), "r"(a[3]), "r"(b0), "r"(b1));
}
__device__ __forceinline__ uint32_t ldu(const float* p) {
    return __float_as_uint(*p);
}
// packed f32x2
__device__ __forceinline__ unsigned long long pk2(float a, float b) {
    unsigned long long r;
    asm("mov.b64 %0, {%1, %2};" : "=l"(r) : "f"(a), "f"(b));
    return r;
}
__device__ __forceinline__ void fma2(unsigned long long& d, unsigned long long a, unsigned long long b) {
    asm("fma.rn.f32x2 %0, %1, %2, %0;" : "+l"(d) : "l"(a), "l"(b));
}
__device__ __forceinline__ void unpk2(unsigned long long v, float& a, float& b) {
    asm("mov.b64 {%0, %1}, %2;" : "=f"(a), "=f"(b) : "l"(v));
}

// ============================================================================
// Projection kernel: 256 CTAs x 256 threads, 64 rows each, f32x2 FFMA.
// Outputs: g bf16 hi/lo (row-major u32 pairs), f^T bf16 B-fragments, h quads.
// ============================================================================
#define PROJ_SMEM_BYTES ((64*257 + 256*64)*4)

__global__ __launch_bounds__(256) void proj_kernel(
    const float* __restrict__ x,
    const float* __restrict__ Wf, const float* __restrict__ bf,
    const float* __restrict__ Wg, const float* __restrict__ bg,
    const float* __restrict__ Wh, const float* __restrict__ bh)
{
    extern __shared__ float sm[];
    float* xs = sm;               // [64][257]
    float* ws = sm + 64*257;      // [256][64]; reused for staging
    const int t    = threadIdx.x;
    const int R0   = blockIdx.x * 64;
    const int bb   = R0 >> 12;
    const int key0 = R0 & (NN-1);

    {
        const float4* xg = (const float4*)(x + (size_t)R0*NC);
        #pragma unroll
        for (int s = 0; s < 16; s++) {
            int idx = t + 256*s;
            int row = idx >> 6, k4 = idx & 63;
            float4 v = xg[idx];
            float* dst = &xs[row*257 + k4*4];
            dst[0]=v.x; dst[1]=v.y; dst[2]=v.z; dst[3]=v.w;
        }
    }

    const int c0 = (t & 15) * 4;
    const int r0 = (t >> 4) * 4;

    for (int ph = 0; ph < 5; ph++) {
        __syncthreads();
        if (ph == 0) {
            #pragma unroll
            for (int s = 0; s < 32; s++) {
                int idx = t + 256*s;
                int k = idx >> 5, c = idx & 31;
                ws[k*64 + c]      = Wf[idx];
                ws[k*64 + 32 + c] = Wg[idx];
            }
        } else {
            const float* whp = Wh + (ph-1)*64;
            #pragma unroll
            for (int s = 0; s < 64; s++) {
                int idx = t + 256*s;
                int k = idx >> 6, c = idx & 63;
                ws[k*64 + c] = whp[k*NC + c];
            }
        }
        __syncthreads();

        unsigned long long accA[4], accB[4];
        #pragma unroll
        for (int a = 0; a < 4; a++) { accA[a] = 0ull; accB[a] = 0ull; }

        #pragma unroll 2
        for (int kk = 0; kk < 128; kk++) {
            int k = kk*2;
            float4 wv0 = *(const float4*)&ws[k*64 + c0];
            float4 wv1 = *(const float4*)&ws[(k+1)*64 + c0];
            unsigned long long wA0 = pk2(wv0.x, wv0.y), wB0 = pk2(wv0.z, wv0.w);
            unsigned long long wA1 = pk2(wv1.x, wv1.y), wB1 = pk2(wv1.z, wv1.w);
            #pragma unroll
            for (int rr = 0; rr < 4; rr++) {
                float x0 = xs[(r0+rr)*257 + k];       // scalar LDS (odd stride)
                float x1 = xs[(r0+rr)*257 + k + 1];
                unsigned long long xb0 = pk2(x0, x0);
                unsigned long long xb1 = pk2(x1, x1);
                fma2(accA[rr], xb0, wA0);
                fma2(accB[rr], xb0, wB0);
                fma2(accA[rr], xb1, wA1);
                fma2(accB[rr], xb1, wB1);
            }
        }

        if (ph == 0) {
            __syncthreads();          // done reading ws; reuse as f staging
            float* s_f = ws;                  // [64 keys][33] fp32 (f + bias)
            #pragma unroll
            for (int rr = 0; rr < 4; rr++) {
                int lrow = r0 + rr;
                int grow = R0 + lrow;
                float v[4];
                unpk2(accA[rr], v[0], v[1]);
                unpk2(accB[rr], v[2], v[3]);
                if (c0 < 32) {
                    #pragma unroll
                    for (int q = 0; q < 4; q++)
                        s_f[lrow*33 + c0 + q] = v[q] + bf[c0 + q];
                } else {
                    float w0 = v[0] + bg[c0-32], w1 = v[1] + bg[c0-31];
                    float w2 = v[2] + bg[c0-30], w3 = v[3] + bg[c0-29];
                    uint32_t h0 = packbf(w0, w1);
                    uint32_t l0 = packbf(w0 - bf_lo(h0), w1 - bf_hi(h0));
                    uint32_t h1 = packbf(w2, w3);
                    uint32_t l1 = packbf(w2 - bf_lo(h1), w3 - bf_hi(h1));
                    int cu = (c0 - 32) >> 1;
                    d_gbh[(size_t)grow*16 + cu    ] = h0;
                    d_gbl[(size_t)grow*16 + cu    ] = l0;
                    d_gbh[(size_t)grow*16 + cu + 1] = h1;
                    d_gbl[(size_t)grow*16 + cu + 1] = l1;
                }
            }
            __syncthreads();
            // f^T B-fragment writes: 512 uint2 entries per array
            #pragma unroll
            for (int j = 0; j < 2; j++) {
                int idx = t + 256*j;              // 0..511
                int key = idx >> 3, e = idx & 7;
                int ks = e >> 2, tq2 = e & 3;
                int cb = 16*ks + 2*tq2;
                const float* fr = s_f + key*33;
                float v0 = fr[cb], v1 = fr[cb+1], v8 = fr[cb+8], v9 = fr[cb+9];
                uint32_t hx = packbf(v0, v1);
                uint32_t hy = packbf(v8, v9);
                uint32_t lx = packbf(v0 - bf_lo(hx), v1 - bf_hi(hx));
                uint32_t ly = packbf(v8 - bf_lo(hy), v9 - bf_hi(hy));
                size_t dst = ((size_t)(bb*NN) + key0 + key)*8 + e;
                d_fqh[dst] = make_uint2(hx, hy);
                d_fql[dst] = make_uint2(lx, ly);
            }
        } else {
            __syncthreads();          // done reading ws; reuse as h staging
            float* sh = ws;                   // [64 keys][65]
            #pragma unroll
            for (int rr = 0; rr < 4; rr++) {
                int lrow = r0 + rr;
                float v[4];
                unpk2(accA[rr], v[0], v[1]);
                unpk2(accB[rr], v[2], v[3]);
                #pragma unroll
                for (int q = 0; q < 4; q++) {
                    int c = c0 + q;
                    sh[lrow*65 + c] = tf32r(v[q] + bh[(ph-1)*64 + c]);
                }
            }
            __syncthreads();
            // h quad writes: 1024 quads per phase
            #pragma unroll
            for (int j = 0; j < 4; j++) {
                int idx = t + 256*j;              // 0..1023
                int kp = idx >> 5, c32 = idx & 31;
                int k1 = ((kp >> 2) << 3) + (kp & 3);
                size_t dst = ((size_t)(bb*2048 + (key0 >> 1) + kp))*128 + (ph-1)*32 + c32;
                d_hq[dst] = make_float4(sh[k1*65 + c32],      sh[(k1+4)*65 + c32],
                                        sh[k1*65 + c32 + 32], sh[(k1+4)*65 + c32 + 32]);
            }
        }
    }
}

// ============================================================================
// Flash attention. Grid (64,4) = 256 CTAs, 256 threads (8 warps), 2 CTAs/SM.
// BM=64 queries, BN=32 keys per tile.
// QK: bf16x2 3-term m16n8k16, warp = 16q x 16k (qg=w>>1, kg=w&1).
// PV: tf32 m16n8k8,          warp = 32q x 64c (mg=w>>2, ng=w&3).
// ============================================================================
#define FB_BYTES   3072                     // 32 keys x 96B (stride 12 uint2)
#define OFF_HQ_B   (4*FB_BYTES)             // 12288
#define HQ_TILE_B  33280                    // 16 kp x 130 float4 x 16B
#define OFF_P_B    (OFF_HQ_B + 2*HQ_TILE_B) // 78848
#define P_STRIDE   36
#define OFF_LS_B   (OFF_P_B + 64*P_STRIDE*4)   // 88064
#define ATT_SMEM_BYTES (OFF_LS_B + 512)     // 88576 (2 CTAs/SM)

__device__ __forceinline__ void attn_load_tile(uint32_t smb, int bb, int kb, int buf, int t) {
    // f B-fragments hi/lo: 256 cpa16 (exactly one per thread)
    {
        int arr = t >> 7, rem = t & 127;
        int key = rem >> 2, ep = rem & 3;
        const uint2* src = (arr ? d_fql : d_fqh)
                         + ((size_t)(bb*NN + kb*BN + key))*8 + ep*2;
        cpa16(smb + (uint32_t)((buf*2+arr)*FB_BYTES + key*96 + ep*16), src);
    }
    // h quads: 2048 cpa16
    #pragma unroll
    for (int s = 0; s < 8; s++) {
        int idx = t + 256*s;
        int kp = idx >> 7, q = idx & 127;           // kp 0..15
        const float4* src = d_hq + ((size_t)(bb*2048 + kb*16 + kp))*128 + q;
        cpa16(smb + (uint32_t)(OFF_HQ_B + buf*HQ_TILE_B + (kp*130 + q)*16), src);
    }
}

__global__ __launch_bounds__(256, 2) void attn_kernel(
    const float* __restrict__ x, float* __restrict__ out)
{
    extern __shared__ char smraw[];
    const uint32_t smb = smem_u32(smraw);
    const int t    = threadIdx.x;
    const int w    = t >> 5, lane = t & 31;
    const int g    = lane >> 2, tq = lane & 3;
    const int bb   = blockIdx.y;
    const int q0   = blockIdx.x * BM;

    const int qg = w >> 1, kg = w & 1;    // QK: 4 qgroups x 2 kgroups
    const int mg = w >> 2, ng = w & 3;    // PV: 2 mgroups x 4 ngroups

    float* P  = (float*)(smraw + OFF_P_B);
    float* LS = (float*)(smraw + OFF_LS_B);
    if (t < 128) LS[t] = 0.f;

    // hoisted QK A fragments (g bf16 hi/lo pairs)
    uint32_t ahi[2][4], alo[2][4];
    {
        const uint32_t* gbh = d_gbh + ((size_t)(bb*NN + q0 + qg*16))*16;
        const uint32_t* gbl = d_gbl + ((size_t)(bb*NN + q0 + qg*16))*16;
        #pragma unroll
        for (int ks = 0; ks < 2; ks++) {
            int cc = 8*ks + tq;
            ahi[ks][0] = gbh[g*16 + cc];
            ahi[ks][1] = gbh[(g+8)*16 + cc];
            ahi[ks][2] = gbh[g*16 + cc + 4];
            ahi[ks][3] = gbh[(g+8)*16 + cc + 4];
            alo[ks][0] = gbl[g*16 + cc];
            alo[ks][1] = gbl[(g+8)*16 + cc];
            alo[ks][2] = gbl[g*16 + cc + 4];
            alo[ks][3] = gbl[(g+8)*16 + cc + 4];
        }
    }

    float oacc[2][8][4];
    #pragma unroll
    for (int a=0;a<2;a++)
        #pragma unroll
        for (int b2=0;b2<8;b2++)
            #pragma unroll
            for (int c=0;c<4;c++) oacc[a][b2][c]=0.f;

    attn_load_tile(smb, bb, 0, 0, t);
    cpa_commit();

    #pragma unroll 1
    for (int kb = 0; kb < NT; kb++) {
        const int pb = kb & 1;
        // Safe: trailing __syncthreads of the previous iteration guarantees
        // all reads of buffer pb^1 are complete before this prefetch.
        if (kb + 1 < NT) attn_load_tile(smb, bb, kb+1, pb^1, t);
        cpa_commit();
        cpa_wait<1>();
        __syncthreads();

        // ---- QK: S(16q x 16k per warp), bf16x2 3-term ----
        const uint2* fbh = (const uint2*)(smraw + (pb*2+0)*FB_BYTES);
        const uint2* fbl = (const uint2*)(smraw + (pb*2+1)*FB_BYTES);
        float sacc[2][4];
        #pragma unroll
        for (int nt=0;nt<2;nt++)
            #pragma unroll
            for (int c=0;c<4;c++) sacc[nt][c]=0.f;

        #pragma unroll
        for (int ks = 0; ks < 2; ks++) {
            #pragma unroll
            for (int nt = 0; nt < 2; nt++) {
                int key = kg*16 + nt*8 + g;
                uint2 qh = fbh[key*12 + ks*4 + tq];
                uint2 ql = fbl[key*12 + ks*4 + tq];
                mma16(sacc[nt], ahi[ks], ql.x, ql.y);
                mma16(sacc[nt], alo[ks], qh.x, qh.y);
                mma16(sacc[nt], ahi[ks], qh.x, qh.y);
            }
        }

        // ---- exp, row sums, P store (tf32-rounded for MMA consistency) ----
        float rs0 = 0.f, rs1 = 0.f;
        #pragma unroll
        for (int nt = 0; nt < 2; nt++) {
            float p0 = tf32r(__expf(sacc[nt][0]));
            float p1 = tf32r(__expf(sacc[nt][1]));
            float p2 = tf32r(__expf(sacc[nt][2]));
            float p3 = tf32r(__expf(sacc[nt][3]));
            rs0 += p0 + p1;
            rs1 += p2 + p3;
            int colb = kg*16 + nt*8 + 2*tq;
            *(float2*)&P[(qg*16+g  )*P_STRIDE + colb] = make_float2(p0, p1);
            *(float2*)&P[(qg*16+g+8)*P_STRIDE + colb] = make_float2(p2, p3);
        }
        rs0 += __shfl_xor_sync(0xffffffffu, rs0, 1);
        rs0 += __shfl_xor_sync(0xffffffffu, rs0, 2);
        rs1 += __shfl_xor_sync(0xffffffffu, rs1, 1);
        rs1 += __shfl_xor_sync(0xffffffffu, rs1, 2);
        if (tq == 0) {
            LS[kg*64 + qg*16 + g    ] += rs0;
            LS[kg*64 + qg*16 + g + 8] += rs1;
        }

        // P half ready: QK warps {4mg..4mg+3} wrote exactly the P rows that
        // PV warps {4mg..4mg+3} read — sync only within the 128-thread group.
        barx(1 + mg, 128);

        // ---- PV: O(32q x 64c per warp) += P * H, tf32 quad B loads ----
        const float4* hq = (const float4*)(smraw + OFF_HQ_B + pb*HQ_TILE_B);
        #pragma unroll
        for (int ks = 0; ks < 4; ks++) {
            uint32_t pa[2][4];
            #pragma unroll
            for (int mt = 0; mt < 2; mt++) {
                const float* Pr = P + (mg*32 + mt*16)*P_STRIDE + ks*8;
                pa[mt][0] = ldu(Pr + g*P_STRIDE + tq);
                pa[mt][1] = ldu(Pr + (g+8)*P_STRIDE + tq);
                pa[mt][2] = ldu(Pr + g*P_STRIDE + tq + 4);
                pa[mt][3] = ldu(Pr + (g+8)*P_STRIDE + tq + 4);
            }
            int rowb = (ks*4 + tq)*130;
            #pragma unroll
            for (int ntl = 0; ntl < 4; ntl++) {
                float4 h4 = hq[rowb + ng*32 + ntl*8 + g];
                mma8(oacc[0][ntl],   pa[0], h4.x, h4.y);
                mma8(oacc[1][ntl],   pa[1], h4.x, h4.y);
                mma8(oacc[0][ntl+4], pa[0], h4.z, h4.w);
                mma8(oacc[1][ntl+4], pa[1], h4.z, h4.w);
            }
        }

        // Protects buffer pb^1 (prefetch target next iter) and P/LS reuse.
        __syncthreads();
    }

    // ---- epilogue: out = x + O / l ----
    #pragma unroll
    for (int mt = 0; mt < 2; mt++) {
        int r0 = mg*32 + mt*16 + g;
        float inv0 = 1.0f / (LS[r0    ] + LS[64 + r0    ]);
        float inv1 = 1.0f / (LS[r0 + 8] + LS[64 + r0 + 8]);
        #pragma unroll
        for (int nt = 0; nt < 8; nt++) {
            int col = ng*64 + nt*8 + 2*tq;
            size_t base0 = ((size_t)(bb*NN + q0 + r0))*NC + col;
            size_t base1 = base0 + (size_t)8*NC;
            float2 xv0 = *(const float2*)(x + base0);
            float2 xv1 = *(const float2*)(x + base1);
            float2 o0, o1;
            o0.x = xv0.x + oacc[mt][nt][0]*inv0;
            o0.y = xv0.y + oacc[mt][nt][1]*inv0;
            o1.x = xv1.x + oacc[mt][nt][2]*inv1;
            o1.y = xv1.y + oacc[mt][nt][3]*inv1;
            *(float2*)(out + base0) = o0;
            *(float2*)(out + base1) = o1;
        }
    }
}

extern "C" void kernel_launch(void* const* d_in, const int* in_sizes, int n_in,
                              void* d_out, int out_size) {
    (void)in_sizes; (void)n_in; (void)out_size;
    const float* x  = (const float*)d_in[0];
    const float* Wf = (const float*)d_in[1];
    const float* bf = (const float*)d_in[2];
    const float* Wg = (const float*)d_in[3];
    const float* bg = (const float*)d_in[4];
    const float* Wh = (const float*)d_in[5];
    const float* bh = (const float*)d_in[6];
    float* out = (float*)d_out;

    cudaFuncSetAttribute(proj_kernel, cudaFuncAttributeMaxDynamicSharedMemorySize,
                         PROJ_SMEM_BYTES);
    cudaFuncSetAttribute(attn_kernel, cudaFuncAttributeMaxDynamicSharedMemorySize,
                         ATT_SMEM_BYTES);

    proj_kernel<<<(NB*NN)/64, 256, PROJ_SMEM_BYTES>>>(x, Wf, bf, Wg, bg, Wh, bh);

    dim3 grid(NN/BM, NB);
    attn_kernel<<<grid, 256, ATT_SMEM_BYTES>>>(x, out);
}

// round 10
// speedup vs baseline: 1.0222x; 1.0222x over previous
#include <cuda_runtime.h>
#include <cstdint>

#define NB 4
#define NN 4096
#define ND 32
#define NC 256
#define BM 128
#define BN 64
#define NT (NN/BN)

// ---------------- scratch (device globals; allocation-free rule) -----------
// g as bf16 hi/lo pairs, row-major: u32[row][16], u32 j = (g[row][2j], g[row][2j+1])
__device__ uint32_t d_gbh[NB*NN*16];
__device__ uint32_t d_gbl[NB*NN*16];
// f^T B-fragments: uint2[b][key][8]; entry e=(ks*4+tq):
//   .x = pack(f[key][16ks+2tq], f[key][16ks+2tq+1])   (b0: k-rows 2tq,2tq+1)
//   .y = pack(f[key][16ks+2tq+8], f[key][16ks+2tq+9]) (b1: k-rows +8)
__device__ uint2 d_fqh[NB*NN*8];
__device__ uint2 d_fql[NB*NN*8];
// h quads (tf32): [b][kp][q] = (h[k1][c], h[k1+4][c], h[k1][c+32], h[k1+4][c+32])
//   kp = (k1>>3)*4 + (k1&3);  q = (c>>6)*32 + (c&31)  (c&63<32)
__device__ float4 d_hq[NB*2048*128];

// ---------------- helpers ---------------------------------------------------
__device__ __forceinline__ uint32_t smem_u32(const void* p) {
    return (uint32_t)__cvta_generic_to_shared(p);
}
__device__ __forceinline__ void cpa16(uint32_t dst, const void* src) {
    asm volatile("cp.async.cg.shared.global [%0], [%1], 16;" :: "r"(dst), "l"(src));
}
__device__ __forceinline__ void cpa_commit() {
    asm volatile("cp.async.commit_group;" ::: "memory");
}
template<int N> __device__ __forceinline__ void cpa_wait() {
    asm volatile("cp.async.wait_group %0;" :: "n"(N) : "memory");
}
__device__ __forceinline__ void barx(int id, int cnt) {
    asm volatile("bar.sync %0, %1;" :: "r"(id), "r"(cnt) : "memory");
}
__device__ __forceinline__ float tf32r(float v) {
    uint32_t r;
    asm("cvt.rna.tf32.f32 %0, %1;" : "=r"(r) : "f"(v));
    return __uint_as_float(r);
}
// bf16x2 pack: low half = lo element, high half = hi element
__device__ __forceinline__ uint32_t packbf(float lo, float hi) {
    uint32_t r;
    asm("cvt.rn.bf16x2.f32 %0, %1, %2;" : "=r"(r) : "f"(hi), "f"(lo));
    return r;
}
__device__ __forceinline__ float bf_lo(uint32_t p) { return __uint_as_float(p << 16); }
__device__ __forceinline__ float bf_hi(uint32_t p) { return __uint_as_float(p & 0xffff0000u); }

// tf32 m16n8k8 (PV)
__device__ __forceinline__ void mma8(float* c, const uint32_t* a, float b0, float b1) {
    asm volatile("mma.sync.aligned.m16n8k8.row.col.f32.tf32.tf32.f32 "
        "{%0,%1,%2,%3}, {%4,%5,%6,%7}, {%8,%9}, {%0,%1,%2,%3};"
        : "+f"(c[0]), "+f"(c[1]), "+f"(c[2]), "+f"(c[3])
        : "r"(a[0]), "r"(a[1]), "r"(a[2]), "r"(a[3]),
          "r"(__float_as_uint(b0)), "r"(__float_as_uint(b1)));
}
// bf16 m16n8k16 (QK)
__device__ __forceinline__ void mma16(float* c, const uint32_t* a, uint32_t b0, uint32_t b1) {
    asm volatile("mma.sync.aligned.m16n8k16.row.col.f32.bf16.bf16.f32 "
        "{%0,%1,%2,%3}, {%4,%5,%6,%7}, {%8,%9}, {%0,%1,%2,%3};"
        : "+f"(c[0]), "+f"(c[1]), "+f"(c[2]), "+f"(c[3])
        : "r"(a[0]), "r"(a[1]), "r"(a[2]), "r"(a[3]), "r"(b0), "r"(b1));
}
__device__ __forceinline__ uint32_t ldu(const float* p) {
    return __float_as_uint(*p);
}
// packed f32x2
__device__ __forceinline__ unsigned long long pk2(float a, float b) {
    unsigned long long r;
    asm("mov.b64 %0, {%1, %2};" : "=l"(r) : "f"(a), "f"(b));
    return r;
}
__device__ __forceinline__ void fma2(unsigned long long& d, unsigned long long a, unsigned long long b) {
    asm("fma.rn.f32x2 %0, %1, %2, %0;" : "+l"(d) : "l"(a), "l"(b));
}
__device__ __forceinline__ void unpk2(unsigned long long v, float& a, float& b) {
    asm("mov.b64 {%0, %1}, %2;" : "=f"(a), "=f"(b) : "l"(v));
}

// ============================================================================
// Projection kernel: 256 CTAs x 512 threads, 64 rows each, f32x2 FFMA.
// Each thread: 4 rows x 2 cols (16 warps/SM for latency hiding; math and
// accumulation order identical to the 256-thread version => bit-identical).
// ============================================================================
#define PROJ_SMEM_BYTES ((64*257 + 256*64)*4)

__global__ __launch_bounds__(512) void proj_kernel(
    const float* __restrict__ x,
    const float* __restrict__ Wf, const float* __restrict__ bf,
    const float* __restrict__ Wg, const float* __restrict__ bg,
    const float* __restrict__ Wh, const float* __restrict__ bh)
{
    extern __shared__ float sm[];
    float* xs = sm;               // [64][257]
    float* ws = sm + 64*257;      // [256][64]; reused for staging
    const int t    = threadIdx.x;
    const int R0   = blockIdx.x * 64;
    const int bb   = R0 >> 12;
    const int key0 = R0 & (NN-1);

    {
        const float4* xg = (const float4*)(x + (size_t)R0*NC);
        #pragma unroll
        for (int s = 0; s < 8; s++) {
            int idx = t + 512*s;
            int row = idx >> 6, k4 = idx & 63;
            float4 v = xg[idx];
            float* dst = &xs[row*257 + k4*4];
            dst[0]=v.x; dst[1]=v.y; dst[2]=v.z; dst[3]=v.w;
        }
    }

    const int c0 = (t & 31) * 2;   // 2 output cols per thread
    const int r0 = (t >> 5) * 4;   // 4 rows per thread

    for (int ph = 0; ph < 5; ph++) {
        __syncthreads();
        if (ph == 0) {
            #pragma unroll
            for (int s = 0; s < 16; s++) {
                int idx = t + 512*s;
                int k = idx >> 5, c = idx & 31;
                ws[k*64 + c]      = Wf[idx];
                ws[k*64 + 32 + c] = Wg[idx];
            }
        } else {
            const float* whp = Wh + (ph-1)*64;
            #pragma unroll
            for (int s = 0; s < 32; s++) {
                int idx = t + 512*s;
                int k = idx >> 6, c = idx & 63;
                ws[k*64 + c] = whp[k*NC + c];
            }
        }
        __syncthreads();

        unsigned long long accA[4];
        #pragma unroll
        for (int a = 0; a < 4; a++) accA[a] = 0ull;

        #pragma unroll 2
        for (int kk = 0; kk < 128; kk++) {
            int k = kk*2;
            float2 wv0 = *(const float2*)&ws[k*64 + c0];
            float2 wv1 = *(const float2*)&ws[(k+1)*64 + c0];
            unsigned long long wA0 = pk2(wv0.x, wv0.y);
            unsigned long long wA1 = pk2(wv1.x, wv1.y);
            #pragma unroll
            for (int rr = 0; rr < 4; rr++) {
                float x0 = xs[(r0+rr)*257 + k];       // scalar LDS (odd stride)
                float x1 = xs[(r0+rr)*257 + k + 1];
                unsigned long long xb0 = pk2(x0, x0);
                unsigned long long xb1 = pk2(x1, x1);
                fma2(accA[rr], xb0, wA0);
                fma2(accA[rr], xb1, wA1);
            }
        }

        if (ph == 0) {
            __syncthreads();          // done reading ws; reuse as f staging
            float* s_f = ws;                  // [64 keys][33] fp32 (f + bias)
            #pragma unroll
            for (int rr = 0; rr < 4; rr++) {
                int lrow = r0 + rr;
                int grow = R0 + lrow;
                float v0, v1;
                unpk2(accA[rr], v0, v1);
                if (c0 < 32) {
                    s_f[lrow*33 + c0    ] = v0 + bf[c0];
                    s_f[lrow*33 + c0 + 1] = v1 + bf[c0+1];
                } else {
                    float w0 = v0 + bg[c0-32], w1 = v1 + bg[c0-31];
                    uint32_t h0 = packbf(w0, w1);
                    uint32_t l0 = packbf(w0 - bf_lo(h0), w1 - bf_hi(h0));
                    int cu = (c0 - 32) >> 1;
                    d_gbh[(size_t)grow*16 + cu] = h0;
                    d_gbl[(size_t)grow*16 + cu] = l0;
                }
            }
            __syncthreads();
            // f^T B-fragment writes: 512 uint2 entries per array (one/thread)
            {
                int key = t >> 3, e = t & 7;
                int ks = e >> 2, tq2 = e & 3;
                int cb = 16*ks + 2*tq2;
                const float* fr = s_f + key*33;
                float v0 = fr[cb], v1 = fr[cb+1], v8 = fr[cb+8], v9 = fr[cb+9];
                uint32_t hx = packbf(v0, v1);
                uint32_t hy = packbf(v8, v9);
                uint32_t lx = packbf(v0 - bf_lo(hx), v1 - bf_hi(hx));
                uint32_t ly = packbf(v8 - bf_lo(hy), v9 - bf_hi(hy));
                size_t dst = ((size_t)(bb*NN) + key0 + key)*8 + e;
                d_fqh[dst] = make_uint2(hx, hy);
                d_fql[dst] = make_uint2(lx, ly);
            }
        } else {
            __syncthreads();          // done reading ws; reuse as h staging
            float* sh = ws;                   // [64 keys][65]
            #pragma unroll
            for (int rr = 0; rr < 4; rr++) {
                int lrow = r0 + rr;
                float v0, v1;
                unpk2(accA[rr], v0, v1);
                sh[lrow*65 + c0    ] = tf32r(v0 + bh[(ph-1)*64 + c0]);
                sh[lrow*65 + c0 + 1] = tf32r(v1 + bh[(ph-1)*64 + c0 + 1]);
            }
            __syncthreads();
            // h quad writes: 1024 quads per phase (2/thread)
            #pragma unroll
            for (int j = 0; j < 2; j++) {
                int idx = t + 512*j;              // 0..1023
                int kp = idx >> 5, c32 = idx & 31;
                int k1 = ((kp >> 2) << 3) + (kp & 3);
                size_t dst = ((size_t)(bb*2048 + (key0 >> 1) + kp))*128 + (ph-1)*32 + c32;
                d_hq[dst] = make_float4(sh[k1*65 + c32],      sh[(k1+4)*65 + c32],
                                        sh[k1*65 + c32 + 32], sh[(k1+4)*65 + c32 + 32]);
            }
        }
    }
}

// ============================================================================
// Flash attention (R8 configuration). Grid (32,4) = 128 CTAs, 512 threads.
// QK: bf16x2 3-term m16n8k16, warp = 16q x 32k (qg=w>>1, kg=w&1).
// PV: tf32 m16n8k8,          warp = 32q x 64c (mg=w>>2, ng=w&3).
// ============================================================================
#define FB_BYTES   6144                     // 64 keys x 96B (stride 12 uint2)
#define OFF_HQ_B   (4*FB_BYTES)             // 24576
#define HQ_TILE_B  66560                    // 32 kp x 130 float4 x 16B
#define OFF_P_B    (OFF_HQ_B + 2*HQ_TILE_B) // 157696
#define P_STRIDE   68
#define OFF_LS_B   (OFF_P_B + 128*P_STRIDE*4)  // 192512
#define ATT_SMEM_BYTES (OFF_LS_B + 1024)    // 193536

__device__ __forceinline__ void attn_load_tile(uint32_t smb, int bb, int kb, int buf, int t) {
    // f B-fragments hi/lo: 512 cpa16 (one per thread)
    {
        int arr = t >> 8, rem = t & 255;
        int key = rem >> 2, ep = rem & 3;
        const uint2* src = (arr ? d_fql : d_fqh)
                         + ((size_t)(bb*NN + kb*64 + key))*8 + ep*2;
        cpa16(smb + (uint32_t)((buf*2+arr)*FB_BYTES + key*96 + ep*16), src);
    }
    // h quads: 4096 cpa16
    #pragma unroll
    for (int s = 0; s < 8; s++) {
        int idx = t + 512*s;
        int kp = idx >> 7, q = idx & 127;
        const float4* src = d_hq + ((size_t)(bb*2048 + kb*32 + kp))*128 + q;
        cpa16(smb + (uint32_t)(OFF_HQ_B + buf*HQ_TILE_B + (kp*130 + q)*16), src);
    }
}

__global__ __launch_bounds__(512, 1) void attn_kernel(
    const float* __restrict__ x, float* __restrict__ out)
{
    extern __shared__ char smraw[];
    const uint32_t smb = smem_u32(smraw);
    const int t    = threadIdx.x;
    const int w    = t >> 5, lane = t & 31;
    const int g    = lane >> 2, tq = lane & 3;
    const int bb   = blockIdx.y;
    const int q0   = blockIdx.x * BM;

    const int qg = w >> 1, kg = w & 1;    // QK: 8 qgroups x 2 kgroups
    const int mg = w >> 2, ng = w & 3;    // PV: 4 mgroups x 4 ngroups

    float* P  = (float*)(smraw + OFF_P_B);
    float* LS = (float*)(smraw + OFF_LS_B);
    if (t < 256) LS[t] = 0.f;

    // hoisted QK A fragments (g bf16 hi/lo pairs)
    uint32_t ahi[2][4], alo[2][4];
    {
        const uint32_t* gbh = d_gbh + ((size_t)(bb*NN + q0 + qg*16))*16;
        const uint32_t* gbl = d_gbl + ((size_t)(bb*NN + q0 + qg*16))*16;
        #pragma unroll
        for (int ks = 0; ks < 2; ks++) {
            int cc = 8*ks + tq;
            ahi[ks][0] = gbh[g*16 + cc];
            ahi[ks][1] = gbh[(g+8)*16 + cc];
            ahi[ks][2] = gbh[g*16 + cc + 4];
            ahi[ks][3] = gbh[(g+8)*16 + cc + 4];
            alo[ks][0] = gbl[g*16 + cc];
            alo[ks][1] = gbl[(g+8)*16 + cc];
            alo[ks][2] = gbl[g*16 + cc + 4];
            alo[ks][3] = gbl[(g+8)*16 + cc + 4];
        }
    }

    float oacc[2][8][4];
    #pragma unroll
    for (int a=0;a<2;a++)
        #pragma unroll
        for (int b2=0;b2<8;b2++)
            #pragma unroll
            for (int c=0;c<4;c++) oacc[a][b2][c]=0.f;

    attn_load_tile(smb, bb, 0, 0, t);
    cpa_commit();

    #pragma unroll 1
    for (int kb = 0; kb < NT; kb++) {
        const int pb = kb & 1;
        // Safe: trailing __syncthreads of the previous iteration guarantees
        // all reads of buffer pb^1 are complete before this prefetch.
        if (kb + 1 < NT) attn_load_tile(smb, bb, kb+1, pb^1, t);
        cpa_commit();
        cpa_wait<1>();
        __syncthreads();

        // ---- QK: S(16q x 32k per warp), bf16x2 3-term ----
        const uint2* fbh = (const uint2*)(smraw + (pb*2+0)*FB_BYTES);
        const uint2* fbl = (const uint2*)(smraw + (pb*2+1)*FB_BYTES);
        float sacc[4][4];
        #pragma unroll
        for (int nt=0;nt<4;nt++)
            #pragma unroll
            for (int c=0;c<4;c++) sacc[nt][c]=0.f;

        #pragma unroll
        for (int ks = 0; ks < 2; ks++) {
            #pragma unroll
            for (int nt = 0; nt < 4; nt++) {
                int key = kg*32 + nt*8 + g;
                uint2 qh = fbh[key*12 + ks*4 + tq];
                uint2 ql = fbl[key*12 + ks*4 + tq];
                mma16(sacc[nt], ahi[ks], ql.x, ql.y);
                mma16(sacc[nt], alo[ks], qh.x, qh.y);
                mma16(sacc[nt], ahi[ks], qh.x, qh.y);
            }
        }

        // ---- exp, row sums, P store (tf32-rounded for MMA consistency) ----
        float rs0 = 0.f, rs1 = 0.f;
        #pragma unroll
        for (int nt = 0; nt < 4; nt++) {
            float p0 = tf32r(__expf(sacc[nt][0]));
            float p1 = tf32r(__expf(sacc[nt][1]));
            float p2 = tf32r(__expf(sacc[nt][2]));
            float p3 = tf32r(__expf(sacc[nt][3]));
            rs0 += p0 + p1;
            rs1 += p2 + p3;
            int colb = kg*32 + nt*8 + 2*tq;
            *(float2*)&P[(qg*16+g  )*P_STRIDE + colb] = make_float2(p0, p1);
            *(float2*)&P[(qg*16+g+8)*P_STRIDE + colb] = make_float2(p2, p3);
        }
        rs0 += __shfl_xor_sync(0xffffffffu, rs0, 1);
        rs0 += __shfl_xor_sync(0xffffffffu, rs0, 2);
        rs1 += __shfl_xor_sync(0xffffffffu, rs1, 1);
        rs1 += __shfl_xor_sync(0xffffffffu, rs1, 2);
        if (tq == 0) {
            LS[kg*128 + qg*16 + g    ] += rs0;
            LS[kg*128 + qg*16 + g + 8] += rs1;
        }

        // P quarter ready: QK warps {4mg..4mg+3} wrote exactly the P rows that
        // PV warps {4mg..4mg+3} read — sync only within the 128-thread group.
        barx(1 + mg, 128);

        // ---- PV: O(32q x 64c per warp) += P * H, tf32 quad B loads ----
        const float4* hq = (const float4*)(smraw + OFF_HQ_B + pb*HQ_TILE_B);
        #pragma unroll
        for (int ks = 0; ks < 8; ks++) {
            uint32_t pa[2][4];
            #pragma unroll
            for (int mt = 0; mt < 2; mt++) {
                const float* Pr = P + (mg*32 + mt*16)*P_STRIDE + ks*8;
                pa[mt][0] = ldu(Pr + g*P_STRIDE + tq);
                pa[mt][1] = ldu(Pr + (g+8)*P_STRIDE + tq);
                pa[mt][2] = ldu(Pr + g*P_STRIDE + tq + 4);
                pa[mt][3] = ldu(Pr + (g+8)*P_STRIDE + tq + 4);
            }
            int rowb = (ks*4 + tq)*130;
            #pragma unroll
            for (int ntl = 0; ntl < 4; ntl++) {
                float4 h4 = hq[rowb + ng*32 + ntl*8 + g];
                mma8(oacc[0][ntl],   pa[0], h4.x, h4.y);
                mma8(oacc[1][ntl],   pa[1], h4.x, h4.y);
                mma8(oacc[0][ntl+4], pa[0], h4.z, h4.w);
                mma8(oacc[1][ntl+4], pa[1], h4.z, h4.w);
            }
        }

        // Protects buffer pb^1 (prefetch target next iter) and P/LS reuse.
        __syncthreads();
    }

    // ---- epilogue: out = x + O / l ----
    #pragma unroll
    for (int mt = 0; mt < 2; mt++) {
        int r0 = mg*32 + mt*16 + g;
        float inv0 = 1.0f / (LS[r0    ] + LS[128 + r0    ]);
        float inv1 = 1.0f / (LS[r0 + 8] + LS[128 + r0 + 8]);
        #pragma unroll
        for (int nt = 0; nt < 8; nt++) {
            int col = ng*64 + nt*8 + 2*tq;
            size_t base0 = ((size_t)(bb*NN + q0 + r0))*NC + col;
            size_t base1 = base0 + (size_t)8*NC;
            float2 xv0 = *(const float2*)(x + base0);
            float2 xv1 = *(const float2*)(x + base1);
            float2 o0, o1;
            o0.x = xv0.x + oacc[mt][nt][0]*inv0;
            o0.y = xv0.y + oacc[mt][nt][1]*inv0;
            o1.x = xv1.x + oacc[mt][nt][2]*inv1;
            o1.y = xv1.y + oacc[mt][nt][3]*inv1;
            *(float2*)(out + base0) = o0;
            *(float2*)(out + base1) = o1;
        }
    }
}

extern "C" void kernel_launch(void* const* d_in, const int* in_sizes, int n_in,
                              void* d_out, int out_size) {
    (void)in_sizes; (void)n_in; (void)out_size;
    const float* x  = (const float*)d_in[0];
    const float* Wf = (const float*)d_in[1];
    const float* bf = (const float*)d_in[2];
    const float* Wg = (const float*)d_in[3];
    const float* bg = (const float*)d_in[4];
    const float* Wh = (const float*)d_in[5];
    const float* bh = (const float*)d_in[6];
    float* out = (float*)d_out;

    cudaFuncSetAttribute(proj_kernel, cudaFuncAttributeMaxDynamicSharedMemorySize,
                         PROJ_SMEM_BYTES);
    cudaFuncSetAttribute(attn_kernel, cudaFuncAttributeMaxDynamicSharedMemorySize,
                         ATT_SMEM_BYTES);

    proj_kernel<<<(NB*NN)/64, 512, PROJ_SMEM_BYTES>>>(x, Wf, bf, Wg, bg, Wh, bh);

    dim3 grid(NN/BM, NB);
    attn_kernel<<<grid, 512, ATT_SMEM_BYTES>>>(x, out);
}

// round 11
// speedup vs baseline: 1.0507x; 1.0279x over previous
#include <cuda_runtime.h>
#include <cstdint>

#define NB 4
#define NN 4096
#define ND 32
#define NC 256
#define BM 128
#define BN 64
#define NT (NN/BN)

// ---------------- scratch (device globals; allocation-free rule) -----------
// g as bf16 hi/lo pairs, row-major: u32[row][16], u32 j = (g[row][2j], g[row][2j+1])
__device__ uint32_t d_gbh[NB*NN*16];
__device__ uint32_t d_gbl[NB*NN*16];
// f^T B-fragments: uint2[b][key][8]; entry e=(ks*4+tq):
//   .x = pack(f[key][16ks+2tq], f[key][16ks+2tq+1])   (b0: k-rows 2tq,2tq+1)
//   .y = pack(f[key][16ks+2tq+8], f[key][16ks+2tq+9]) (b1: k-rows +8)
__device__ uint2 d_fqh[NB*NN*8];
__device__ uint2 d_fql[NB*NN*8];
// h quads (tf32): [b][kp][q] = (h[k1][c], h[k1+4][c], h[k1][c+32], h[k1+4][c+32])
//   kp = (k1>>3)*4 + (k1&3);  q = (c>>6)*32 + (c&31)  (c&63<32)
__device__ float4 d_hq[NB*2048*128];

// ---------------- helpers ---------------------------------------------------
__device__ __forceinline__ uint32_t smem_u32(const void* p) {
    return (uint32_t)__cvta_generic_to_shared(p);
}
__device__ __forceinline__ void cpa16(uint32_t dst, const void* src) {
    asm volatile("cp.async.cg.shared.global [%0], [%1], 16;" :: "r"(dst), "l"(src));
}
__device__ __forceinline__ void cpa_commit() {
    asm volatile("cp.async.commit_group;" ::: "memory");
}
template<int N> __device__ __forceinline__ void cpa_wait() {
    asm volatile("cp.async.wait_group %0;" :: "n"(N) : "memory");
}
__device__ __forceinline__ float tf32r(float v) {
    uint32_t r;
    asm("cvt.rna.tf32.f32 %0, %1;" : "=r"(r) : "f"(v));
    return __uint_as_float(r);
}
// bf16x2 pack: low half = lo element, high half = hi element
__device__ __forceinline__ uint32_t packbf(float lo, float hi) {
    uint32_t r;
    asm("cvt.rn.bf16x2.f32 %0, %1, %2;" : "=r"(r) : "f"(hi), "f"(lo));
    return r;
}
__device__ __forceinline__ float bf_lo(uint32_t p) { return __uint_as_float(p << 16); }
__device__ __forceinline__ float bf_hi(uint32_t p) { return __uint_as_float(p & 0xffff0000u); }

// tf32 m16n8k8 (PV)
__device__ __forceinline__ void mma8(float* c, const uint32_t* a, float b0, float b1) {
    asm volatile("mma.sync.aligned.m16n8k8.row.col.f32.tf32.tf32.f32 "
        "{%0,%1,%2,%3}, {%4,%5,%6,%7}, {%8,%9}, {%0,%1,%2,%3};"
        : "+f"(c[0]), "+f"(c[1]), "+f"(c[2]), "+f"(c[3])
        : "r"(a[0]), "r"(a[1]), "r"(a[2]), "r"(a[3]),
          "r"(__float_as_uint(b0)), "r"(__float_as_uint(b1)));
}
// bf16 m16n8k16 (QK)
__device__ __forceinline__ void mma16(float* c, const uint32_t* a, uint32_t b0, uint32_t b1) {
    asm volatile("mma.sync.aligned.m16n8k16.row.col.f32.bf16.bf16.f32 "
        "{%0,%1,%2,%3}, {%4,%5,%6,%7}, {%8,%9}, {%0,%1,%2,%3};"
        : "+f"(c[0]), "+f"(c[1]), "+f"(c[2]), "+f"(c[3])
        : "r"(a[0]), "r"(a[1]), "r"(a[2]), "r"(a[3]), "r"(b0), "r"(b1));
}
__device__ __forceinline__ uint32_t ldu(const float* p) {
    return __float_as_uint(*p);
}
// packed f32x2
__device__ __forceinline__ unsigned long long pk2(float a, float b) {
    unsigned long long r;
    asm("mov.b64 %0, {%1, %2};" : "=l"(r) : "f"(a), "f"(b));
    return r;
}
__device__ __forceinline__ void fma2(unsigned long long& d, unsigned long long a, unsigned long long b) {
    asm("fma.rn.f32x2 %0, %1, %2, %0;" : "+l"(d) : "l"(a), "l"(b));
}
__device__ __forceinline__ void unpk2(unsigned long long v, float& a, float& b) {
    asm("mov.b64 {%0, %1}, %2;" : "=f"(a), "=f"(b) : "l"(v));
}

// ============================================================================
// Projection kernel (proven R8 config): 256 CTAs x 256 threads, 64 rows each.
// ============================================================================
#define PROJ_SMEM_BYTES ((64*257 + 256*64)*4)

__global__ __launch_bounds__(256) void proj_kernel(
    const float* __restrict__ x,
    const float* __restrict__ Wf, const float* __restrict__ bf,
    const float* __restrict__ Wg, const float* __restrict__ bg,
    const float* __restrict__ Wh, const float* __restrict__ bh)
{
    extern __shared__ float sm[];
    float* xs = sm;               // [64][257]
    float* ws = sm + 64*257;      // [256][64]; reused for staging
    const int t    = threadIdx.x;
    const int R0   = blockIdx.x * 64;
    const int bb   = R0 >> 12;
    const int key0 = R0 & (NN-1);

    {
        const float4* xg = (const float4*)(x + (size_t)R0*NC);
        #pragma unroll
        for (int s = 0; s < 16; s++) {
            int idx = t + 256*s;
            int row = idx >> 6, k4 = idx & 63;
            float4 v = xg[idx];
            float* dst = &xs[row*257 + k4*4];
            dst[0]=v.x; dst[1]=v.y; dst[2]=v.z; dst[3]=v.w;
        }
    }

    const int c0 = (t & 15) * 4;
    const int r0 = (t >> 4) * 4;

    for (int ph = 0; ph < 5; ph++) {
        __syncthreads();
        if (ph == 0) {
            #pragma unroll
            for (int s = 0; s < 32; s++) {
                int idx = t + 256*s;
                int k = idx >> 5, c = idx & 31;
                ws[k*64 + c]      = Wf[idx];
                ws[k*64 + 32 + c] = Wg[idx];
            }
        } else {
            const float* whp = Wh + (ph-1)*64;
            #pragma unroll
            for (int s = 0; s < 64; s++) {
                int idx = t + 256*s;
                int k = idx >> 6, c = idx & 63;
                ws[k*64 + c] = whp[k*NC + c];
            }
        }
        __syncthreads();

        unsigned long long accA[4], accB[4];
        #pragma unroll
        for (int a = 0; a < 4; a++) { accA[a] = 0ull; accB[a] = 0ull; }

        #pragma unroll 2
        for (int kk = 0; kk < 128; kk++) {
            int k = kk*2;
            float4 wv0 = *(const float4*)&ws[k*64 + c0];
            float4 wv1 = *(const float4*)&ws[(k+1)*64 + c0];
            unsigned long long wA0 = pk2(wv0.x, wv0.y), wB0 = pk2(wv0.z, wv0.w);
            unsigned long long wA1 = pk2(wv1.x, wv1.y), wB1 = pk2(wv1.z, wv1.w);
            #pragma unroll
            for (int rr = 0; rr < 4; rr++) {
                float x0 = xs[(r0+rr)*257 + k];       // scalar LDS (odd stride)
                float x1 = xs[(r0+rr)*257 + k + 1];
                unsigned long long xb0 = pk2(x0, x0);
                unsigned long long xb1 = pk2(x1, x1);
                fma2(accA[rr], xb0, wA0);
                fma2(accB[rr], xb0, wB0);
                fma2(accA[rr], xb1, wA1);
                fma2(accB[rr], xb1, wB1);
            }
        }

        if (ph == 0) {
            __syncthreads();          // done reading ws; reuse as f staging
            float* s_f = ws;                  // [64 keys][33] fp32 (f + bias)
            #pragma unroll
            for (int rr = 0; rr < 4; rr++) {
                int lrow = r0 + rr;
                int grow = R0 + lrow;
                float v[4];
                unpk2(accA[rr], v[0], v[1]);
                unpk2(accB[rr], v[2], v[3]);
                if (c0 < 32) {
                    #pragma unroll
                    for (int q = 0; q < 4; q++)
                        s_f[lrow*33 + c0 + q] = v[q] + bf[c0 + q];
                } else {
                    float w0 = v[0] + bg[c0-32], w1 = v[1] + bg[c0-31];
                    float w2 = v[2] + bg[c0-30], w3 = v[3] + bg[c0-29];
                    uint32_t h0 = packbf(w0, w1);
                    uint32_t l0 = packbf(w0 - bf_lo(h0), w1 - bf_hi(h0));
                    uint32_t h1 = packbf(w2, w3);
                    uint32_t l1 = packbf(w2 - bf_lo(h1), w3 - bf_hi(h1));
                    int cu = (c0 - 32) >> 1;
                    d_gbh[(size_t)grow*16 + cu    ] = h0;
                    d_gbl[(size_t)grow*16 + cu    ] = l0;
                    d_gbh[(size_t)grow*16 + cu + 1] = h1;
                    d_gbl[(size_t)grow*16 + cu + 1] = l1;
                }
            }
            __syncthreads();
            // f^T B-fragment writes: 512 uint2 entries per array
            #pragma unroll
            for (int j = 0; j < 2; j++) {
                int idx = t + 256*j;              // 0..511
                int key = idx >> 3, e = idx & 7;
                int ks = e >> 2, tq2 = e & 3;
                int cb = 16*ks + 2*tq2;
                const float* fr = s_f + key*33;
                float v0 = fr[cb], v1 = fr[cb+1], v8 = fr[cb+8], v9 = fr[cb+9];
                uint32_t hx = packbf(v0, v1);
                uint32_t hy = packbf(v8, v9);
                uint32_t lx = packbf(v0 - bf_lo(hx), v1 - bf_hi(hx));
                uint32_t ly = packbf(v8 - bf_lo(hy), v9 - bf_hi(hy));
                size_t dst = ((size_t)(bb*NN) + key0 + key)*8 + e;
                d_fqh[dst] = make_uint2(hx, hy);
                d_fql[dst] = make_uint2(lx, ly);
            }
        } else {
            __syncthreads();          // done reading ws; reuse as h staging
            float* sh = ws;                   // [64 keys][65]
            #pragma unroll
            for (int rr = 0; rr < 4; rr++) {
                int lrow = r0 + rr;
                float v[4];
                unpk2(accA[rr], v[0], v[1]);
                unpk2(accB[rr], v[2], v[3]);
                #pragma unroll
                for (int q = 0; q < 4; q++) {
                    int c = c0 + q;
                    sh[lrow*65 + c] = tf32r(v[q] + bh[(ph-1)*64 + c]);
                }
            }
            __syncthreads();
            // h quad writes: 1024 quads per phase
            #pragma unroll
            for (int j = 0; j < 4; j++) {
                int idx = t + 256*j;              // 0..1023
                int kp = idx >> 5, c32 = idx & 31;
                int k1 = ((kp >> 2) << 3) + (kp & 3);
                size_t dst = ((size_t)(bb*2048 + (key0 >> 1) + kp))*128 + (ph-1)*32 + c32;
                d_hq[dst] = make_float4(sh[k1*65 + c32],      sh[(k1+4)*65 + c32],
                                        sh[k1*65 + c32 + 32], sh[(k1+4)*65 + c32 + 32]);
            }
        }
    }
}

// ============================================================================
// Flash attention, QK/PV software-pipelined by one k-tile.
// Grid (32,4) = 128 CTAs, 512 threads.
// Iter kb: QK(kb)->exp->P[kb&1]; PV(kb-1) from P[(kb-1)&1], h[(kb-1)&1].
// No named barrier: warps fully decoupled between the two global syncs.
// ============================================================================
#define FB_BYTES   6144                     // 64 keys x 96B (stride 12 uint2)
#define OFF_HQ_B   (4*FB_BYTES)             // 24576
#define HQ_TILE_B  66560                    // 32 kp x 130 float4 x 16B
#define OFF_P_B    (OFF_HQ_B + 2*HQ_TILE_B) // 157696
#define P_STRIDE   68
#define P_BUF_B    (128*P_STRIDE*4)         // 34816
#define OFF_LS_B   (OFF_P_B + 2*P_BUF_B)    // 227328
#define ATT_SMEM_BYTES (OFF_LS_B + 1024)    // 228352

__device__ __forceinline__ void attn_load_f(uint32_t smb, int bb, int kb, int buf, int t) {
    // f B-fragments hi/lo: 512 cpa16 (one per thread)
    int arr = t >> 8, rem = t & 255;
    int key = rem >> 2, ep = rem & 3;
    const uint2* src = (arr ? d_fql : d_fqh)
                     + ((size_t)(bb*NN + kb*64 + key))*8 + ep*2;
    cpa16(smb + (uint32_t)((buf*2+arr)*FB_BYTES + key*96 + ep*16), src);
}
__device__ __forceinline__ void attn_load_h(uint32_t smb, int bb, int kb, int buf, int t) {
    // h quads: 4096 cpa16
    #pragma unroll
    for (int s = 0; s < 8; s++) {
        int idx = t + 512*s;
        int kp = idx >> 7, q = idx & 127;
        const float4* src = d_hq + ((size_t)(bb*2048 + kb*32 + kp))*128 + q;
        cpa16(smb + (uint32_t)(OFF_HQ_B + buf*HQ_TILE_B + (kp*130 + q)*16), src);
    }
}

__global__ __launch_bounds__(512, 1) void attn_kernel(
    const float* __restrict__ x, float* __restrict__ out)
{
    extern __shared__ char smraw[];
    const uint32_t smb = smem_u32(smraw);
    const int t    = threadIdx.x;
    const int w    = t >> 5, lane = t & 31;
    const int g    = lane >> 2, tq = lane & 3;
    const int bb   = blockIdx.y;
    const int q0   = blockIdx.x * BM;

    const int qg = w >> 1, kg = w & 1;    // QK: 8 qgroups x 2 kgroups
    const int mg = w >> 2, ng = w & 3;    // PV: 4 mgroups x 4 ngroups

    float* LS = (float*)(smraw + OFF_LS_B);
    if (t < 256) LS[t] = 0.f;

    // hoisted QK A fragments (g bf16 hi/lo pairs)
    uint32_t ahi[2][4], alo[2][4];
    {
        const uint32_t* gbh = d_gbh + ((size_t)(bb*NN + q0 + qg*16))*16;
        const uint32_t* gbl = d_gbl + ((size_t)(bb*NN + q0 + qg*16))*16;
        #pragma unroll
        for (int ks = 0; ks < 2; ks++) {
            int cc = 8*ks + tq;
            ahi[ks][0] = gbh[g*16 + cc];
            ahi[ks][1] = gbh[(g+8)*16 + cc];
            ahi[ks][2] = gbh[g*16 + cc + 4];
            ahi[ks][3] = gbh[(g+8)*16 + cc + 4];
            alo[ks][0] = gbl[g*16 + cc];
            alo[ks][1] = gbl[(g+8)*16 + cc];
            alo[ks][2] = gbl[g*16 + cc + 4];
            alo[ks][3] = gbl[(g+8)*16 + cc + 4];
        }
    }

    float oacc[2][8][4];
    #pragma unroll
    for (int a=0;a<2;a++)
        #pragma unroll
        for (int b2=0;b2<8;b2++)
            #pragma unroll
            for (int c=0;c<4;c++) oacc[a][b2][c]=0.f;

    // prologue: group {f(0)}
    attn_load_f(smb, bb, 0, 0, t);
    cpa_commit();

    #pragma unroll 1
    for (int kb = 0; kb < NT; kb++) {
        const int pb = kb & 1;
        // Issue next-tile loads. Safe: targets' last readers finished before
        // the sync_bottom of iteration kb-1 (f slot: QK(kb-1); h slot kb&1:
        // PV(kb-2); both precede this point in program order).
        if (kb + 1 < NT) attn_load_f(smb, bb, kb+1, pb^1, t);
        cpa_commit();                          // group F(kb+1) (empty on last)
        attn_load_h(smb, bb, kb, pb, t);
        cpa_commit();                          // group H(kb)
        cpa_wait<2>();                         // F(kb), H(kb-1) complete
        __syncthreads();                       // sync_top: publish f(kb), h(kb-1), P[pb^1]

        // ---- QK(kb): S(16q x 32k per warp), bf16x2 3-term ----
        const uint2* fbh = (const uint2*)(smraw + (pb*2+0)*FB_BYTES);
        const uint2* fbl = (const uint2*)(smraw + (pb*2+1)*FB_BYTES);
        float sacc[4][4];
        #pragma unroll
        for (int nt=0;nt<4;nt++)
            #pragma unroll
            for (int c=0;c<4;c++) sacc[nt][c]=0.f;

        #pragma unroll
        for (int ks = 0; ks < 2; ks++) {
            #pragma unroll
            for (int nt = 0; nt < 4; nt++) {
                int key = kg*32 + nt*8 + g;
                uint2 qh = fbh[key*12 + ks*4 + tq];
                uint2 ql = fbl[key*12 + ks*4 + tq];
                mma16(sacc[nt], ahi[ks], ql.x, ql.y);
                mma16(sacc[nt], alo[ks], qh.x, qh.y);
                mma16(sacc[nt], ahi[ks], qh.x, qh.y);
            }
        }

        // ---- exp, row sums, P[pb] store ----
        {
            float* P = (float*)(smraw + OFF_P_B + pb*P_BUF_B);
            float rs0 = 0.f, rs1 = 0.f;
            #pragma unroll
            for (int nt = 0; nt < 4; nt++) {
                float p0 = tf32r(__expf(sacc[nt][0]));
                float p1 = tf32r(__expf(sacc[nt][1]));
                float p2 = tf32r(__expf(sacc[nt][2]));
                float p3 = tf32r(__expf(sacc[nt][3]));
                rs0 += p0 + p1;
                rs1 += p2 + p3;
                int colb = kg*32 + nt*8 + 2*tq;
                *(float2*)&P[(qg*16+g  )*P_STRIDE + colb] = make_float2(p0, p1);
                *(float2*)&P[(qg*16+g+8)*P_STRIDE + colb] = make_float2(p2, p3);
            }
            rs0 += __shfl_xor_sync(0xffffffffu, rs0, 1);
            rs0 += __shfl_xor_sync(0xffffffffu, rs0, 2);
            rs1 += __shfl_xor_sync(0xffffffffu, rs1, 1);
            rs1 += __shfl_xor_sync(0xffffffffu, rs1, 2);
            if (tq == 0) {
                LS[kg*128 + qg*16 + g    ] += rs0;
                LS[kg*128 + qg*16 + g + 8] += rs1;
            }
        }

        // ---- PV(kb-1): O += P[pb^1] * h[pb^1]  (no intra-iter dependence) ----
        if (kb > 0) {
            const float*  Pp = (const float*)(smraw + OFF_P_B + (pb^1)*P_BUF_B);
            const float4* hq = (const float4*)(smraw + OFF_HQ_B + (pb^1)*HQ_TILE_B);
            #pragma unroll
            for (int ks = 0; ks < 8; ks++) {
                uint32_t pa[2][4];
                #pragma unroll
                for (int mt = 0; mt < 2; mt++) {
                    const float* Pr = Pp + (mg*32 + mt*16)*P_STRIDE + ks*8;
                    pa[mt][0] = ldu(Pr + g*P_STRIDE + tq);
                    pa[mt][1] = ldu(Pr + (g+8)*P_STRIDE + tq);
                    pa[mt][2] = ldu(Pr + g*P_STRIDE + tq + 4);
                    pa[mt][3] = ldu(Pr + (g+8)*P_STRIDE + tq + 4);
                }
                int rowb = (ks*4 + tq)*130;
                #pragma unroll
                for (int ntl = 0; ntl < 4; ntl++) {
                    float4 h4 = hq[rowb + ng*32 + ntl*8 + g];
                    mma8(oacc[0][ntl],   pa[0], h4.x, h4.y);
                    mma8(oacc[1][ntl],   pa[1], h4.x, h4.y);
                    mma8(oacc[0][ntl+4], pa[0], h4.z, h4.w);
                    mma8(oacc[1][ntl+4], pa[1], h4.z, h4.w);
                }
            }
        }

        __syncthreads();                       // sync_bottom
    }

    // ---- final PV(NT-1) ----
    cpa_wait<0>();                             // h(NT-1) complete (this thread)
    __syncthreads();                           // all threads' h(NT-1) published
    {
        const int pb = (NT-1) & 1;
        const float*  Pp = (const float*)(smraw + OFF_P_B + pb*P_BUF_B);
        const float4* hq = (const float4*)(smraw + OFF_HQ_B + pb*HQ_TILE_B);
        #pragma unroll
        for (int ks = 0; ks < 8; ks++) {
            uint32_t pa[2][4];
            #pragma unroll
            for (int mt = 0; mt < 2; mt++) {
                const float* Pr = Pp + (mg*32 + mt*16)*P_STRIDE + ks*8;
                pa[mt][0] = ldu(Pr + g*P_STRIDE + tq);
                pa[mt][1] = ldu(Pr + (g+8)*P_STRIDE + tq);
                pa[mt][2] = ldu(Pr + g*P_STRIDE + tq + 4);
                pa[mt][3] = ldu(Pr + (g+8)*P_STRIDE + tq + 4);
            }
            int rowb = (ks*4 + tq)*130;
            #pragma unroll
            for (int ntl = 0; ntl < 4; ntl++) {
                float4 h4 = hq[rowb + ng*32 + ntl*8 + g];
                mma8(oacc[0][ntl],   pa[0], h4.x, h4.y);
                mma8(oacc[1][ntl],   pa[1], h4.x, h4.y);
                mma8(oacc[0][ntl+4], pa[0], h4.z, h4.w);
                mma8(oacc[1][ntl+4], pa[1], h4.z, h4.w);
            }
        }
    }

    // ---- epilogue: out = x + O / l ----
    #pragma unroll
    for (int mt = 0; mt < 2; mt++) {
        int r0 = mg*32 + mt*16 + g;
        float inv0 = 1.0f / (LS[r0    ] + LS[128 + r0    ]);
        float inv1 = 1.0f / (LS[r0 + 8] + LS[128 + r0 + 8]);
        #pragma unroll
        for (int nt = 0; nt < 8; nt++) {
            int col = ng*64 + nt*8 + 2*tq;
            size_t base0 = ((size_t)(bb*NN + q0 + r0))*NC + col;
            size_t base1 = base0 + (size_t)8*NC;
            float2 xv0 = *(const float2*)(x + base0);
            float2 xv1 = *(const float2*)(x + base1);
            float2 o0, o1;
            o0.x = xv0.x + oacc[mt][nt][0]*inv0;
            o0.y = xv0.y + oacc[mt][nt][1]*inv0;
            o1.x = xv1.x + oacc[mt][nt][2]*inv1;
            o1.y = xv1.y + oacc[mt][nt][3]*inv1;
            *(float2*)(out + base0) = o0;
            *(float2*)(out + base1) = o1;
        }
    }
}

extern "C" void kernel_launch(void* const* d_in, const int* in_sizes, int n_in,
                              void* d_out, int out_size) {
    (void)in_sizes; (void)n_in; (void)out_size;
    const float* x  = (const float*)d_in[0];
    const float* Wf = (const float*)d_in[1];
    const float* bf = (const float*)d_in[2];
    const float* Wg = (const float*)d_in[3];
    const float* bg = (const float*)d_in[4];
    const float* Wh = (const float*)d_in[5];
    const float* bh = (const float*)d_in[6];
    float* out = (float*)d_out;

    cudaFuncSetAttribute(proj_kernel, cudaFuncAttributeMaxDynamicSharedMemorySize,
                         PROJ_SMEM_BYTES);
    cudaFuncSetAttribute(attn_kernel, cudaFuncAttributeMaxDynamicSharedMemorySize,
                         ATT_SMEM_BYTES);

    proj_kernel<<<(NB*NN)/64, 256, PROJ_SMEM_BYTES>>>(x, Wf, bf, Wg, bg, Wh, bh);

    dim3 grid(NN/BM, NB);
    attn_kernel<<<grid, 512, ATT_SMEM_BYTES>>>(x, out);
}

// round 12
// speedup vs baseline: 1.3402x; 1.2756x over previous
#include <cuda_runtime.h>
#include <cuda_fp16.h>
#include <cstdint>

#define NB 4
#define NN 4096
#define ND 32
#define NC 256
#define BM 128
#define BN 64
#define NT (NN/BN)

// ---------------- scratch (device globals; allocation-free rule) -----------
// g as bf16 hi/lo pairs, row-major: u32[row][16]
__device__ uint32_t d_gbh[NB*NN*16];
__device__ uint32_t d_gbl[NB*NN*16];
// f^T bf16 B-fragments: uint2[b][key][8] (same as R8)
__device__ uint2 d_fqh[NB*NN*8];
__device__ uint2 d_fql[NB*NN*8];
// h fp16 B-fragment quads: uint4[b][K16][tq][q]; K16 = key>>4 (16-key block),
//  entry (tq, q): .x = f16x2(h[k2][c], h[k2+1][c])   k2 = K16*16+2tq
//                 .y = f16x2(h[k2+8][c], h[k2+9][c])
//                 .z/.w = same for col c+32;  c = (q>>5)*64 + (q&31)
__device__ uint4 d_hf4[NB*256*4*128];

// ---------------- helpers ---------------------------------------------------
__device__ __forceinline__ uint32_t smem_u32(const void* p) {
    return (uint32_t)__cvta_generic_to_shared(p);
}
__device__ __forceinline__ void cpa16(uint32_t dst, const void* src) {
    asm volatile("cp.async.cg.shared.global [%0], [%1], 16;" :: "r"(dst), "l"(src));
}
__device__ __forceinline__ void cpa_commit() {
    asm volatile("cp.async.commit_group;" ::: "memory");
}
template<int N> __device__ __forceinline__ void cpa_wait() {
    asm volatile("cp.async.wait_group %0;" :: "n"(N) : "memory");
}
__device__ __forceinline__ void barx(int id, int cnt) {
    asm volatile("bar.sync %0, %1;" :: "r"(id), "r"(cnt) : "memory");
}
__device__ __forceinline__ float tf32r(float v) {
    uint32_t r;
    asm("cvt.rna.tf32.f32 %0, %1;" : "=r"(r) : "f"(v));
    return __uint_as_float(r);
}
// bf16x2 pack (low half = lo, high half = hi)
__device__ __forceinline__ uint32_t packbf(float lo, float hi) {
    uint32_t r;
    asm("cvt.rn.bf16x2.f32 %0, %1, %2;" : "=r"(r) : "f"(hi), "f"(lo));
    return r;
}
// fp16x2 pack (low half = lo, high half = hi)
__device__ __forceinline__ uint32_t packf16(float lo, float hi) {
    uint32_t r;
    asm("cvt.rn.f16x2.f32 %0, %1, %2;" : "=r"(r) : "f"(hi), "f"(lo));
    return r;
}
__device__ __forceinline__ float bf_lo(uint32_t p) { return __uint_as_float(p << 16); }
__device__ __forceinline__ float bf_hi(uint32_t p) { return __uint_as_float(p & 0xffff0000u); }

// bf16 m16n8k16 (QK)
__device__ __forceinline__ void mma16(float* c, const uint32_t* a, uint32_t b0, uint32_t b1) {
    asm volatile("mma.sync.aligned.m16n8k16.row.col.f32.bf16.bf16.f32 "
        "{%0,%1,%2,%3}, {%4,%5,%6,%7}, {%8,%9}, {%0,%1,%2,%3};"
        : "+f"(c[0]), "+f"(c[1]), "+f"(c[2]), "+f"(c[3])
        : "r"(a[0]), "r"(a[1]), "r"(a[2]), "r"(a[3]), "r"(b0), "r"(b1));
}
// fp16 m16n8k16 (PV)
__device__ __forceinline__ void mma16h(float* c, const uint32_t* a, uint32_t b0, uint32_t b1) {
    asm volatile("mma.sync.aligned.m16n8k16.row.col.f32.f16.f16.f32 "
        "{%0,%1,%2,%3}, {%4,%5,%6,%7}, {%8,%9}, {%0,%1,%2,%3};"
        : "+f"(c[0]), "+f"(c[1]), "+f"(c[2]), "+f"(c[3])
        : "r"(a[0]), "r"(a[1]), "r"(a[2]), "r"(a[3]), "r"(b0), "r"(b1));
}
// packed f32x2
__device__ __forceinline__ unsigned long long pk2(float a, float b) {
    unsigned long long r;
    asm("mov.b64 %0, {%1, %2};" : "=l"(r) : "f"(a), "f"(b));
    return r;
}
__device__ __forceinline__ void fma2(unsigned long long& d, unsigned long long a, unsigned long long b) {
    asm("fma.rn.f32x2 %0, %1, %2, %0;" : "+l"(d) : "l"(a), "l"(b));
}
__device__ __forceinline__ void unpk2(unsigned long long v, float& a, float& b) {
    asm("mov.b64 {%0, %1}, %2;" : "=f"(a), "=f"(b) : "l"(v));
}

// ============================================================================
// Projection kernel (proven R8 mainloop): 256 CTAs x 256 threads, 64 rows.
// Outputs: g bf16 hi/lo, f^T bf16 fragments, h fp16 fragment quads.
// ============================================================================
#define PROJ_SMEM_BYTES ((64*257 + 256*64)*4)

__global__ __launch_bounds__(256) void proj_kernel(
    const float* __restrict__ x,
    const float* __restrict__ Wf, const float* __restrict__ bf,
    const float* __restrict__ Wg, const float* __restrict__ bg,
    const float* __restrict__ Wh, const float* __restrict__ bh)
{
    extern __shared__ float sm[];
    float* xs = sm;               // [64][257]
    float* ws = sm + 64*257;      // [256][64]; reused for staging
    const int t    = threadIdx.x;
    const int R0   = blockIdx.x * 64;
    const int bb   = R0 >> 12;
    const int key0 = R0 & (NN-1);

    {
        const float4* xg = (const float4*)(x + (size_t)R0*NC);
        #pragma unroll
        for (int s = 0; s < 16; s++) {
            int idx = t + 256*s;
            int row = idx >> 6, k4 = idx & 63;
            float4 v = xg[idx];
            float* dst = &xs[row*257 + k4*4];
            dst[0]=v.x; dst[1]=v.y; dst[2]=v.z; dst[3]=v.w;
        }
    }

    const int c0 = (t & 15) * 4;
    const int r0 = (t >> 4) * 4;

    for (int ph = 0; ph < 5; ph++) {
        __syncthreads();
        if (ph == 0) {
            #pragma unroll
            for (int s = 0; s < 32; s++) {
                int idx = t + 256*s;
                int k = idx >> 5, c = idx & 31;
                ws[k*64 + c]      = Wf[idx];
                ws[k*64 + 32 + c] = Wg[idx];
            }
        } else {
            const float* whp = Wh + (ph-1)*64;
            #pragma unroll
            for (int s = 0; s < 64; s++) {
                int idx = t + 256*s;
                int k = idx >> 6, c = idx & 63;
                ws[k*64 + c] = whp[k*NC + c];
            }
        }
        __syncthreads();

        unsigned long long accA[4], accB[4];
        #pragma unroll
        for (int a = 0; a < 4; a++) { accA[a] = 0ull; accB[a] = 0ull; }

        #pragma unroll 2
        for (int kk = 0; kk < 128; kk++) {
            int k = kk*2;
            float4 wv0 = *(const float4*)&ws[k*64 + c0];
            float4 wv1 = *(const float4*)&ws[(k+1)*64 + c0];
            unsigned long long wA0 = pk2(wv0.x, wv0.y), wB0 = pk2(wv0.z, wv0.w);
            unsigned long long wA1 = pk2(wv1.x, wv1.y), wB1 = pk2(wv1.z, wv1.w);
            #pragma unroll
            for (int rr = 0; rr < 4; rr++) {
                float x0 = xs[(r0+rr)*257 + k];       // scalar LDS (odd stride)
                float x1 = xs[(r0+rr)*257 + k + 1];
                unsigned long long xb0 = pk2(x0, x0);
                unsigned long long xb1 = pk2(x1, x1);
                fma2(accA[rr], xb0, wA0);
                fma2(accB[rr], xb0, wB0);
                fma2(accA[rr], xb1, wA1);
                fma2(accB[rr], xb1, wB1);
            }
        }

        if (ph == 0) {
            __syncthreads();          // done reading ws; reuse as f staging
            float* s_f = ws;                  // [64 keys][33] fp32 (f + bias)
            #pragma unroll
            for (int rr = 0; rr < 4; rr++) {
                int lrow = r0 + rr;
                int grow = R0 + lrow;
                float v[4];
                unpk2(accA[rr], v[0], v[1]);
                unpk2(accB[rr], v[2], v[3]);
                if (c0 < 32) {
                    #pragma unroll
                    for (int q = 0; q < 4; q++)
                        s_f[lrow*33 + c0 + q] = v[q] + bf[c0 + q];
                } else {
                    float w0 = v[0] + bg[c0-32], w1 = v[1] + bg[c0-31];
                    float w2 = v[2] + bg[c0-30], w3 = v[3] + bg[c0-29];
                    uint32_t h0 = packbf(w0, w1);
                    uint32_t l0 = packbf(w0 - bf_lo(h0), w1 - bf_hi(h0));
                    uint32_t h1 = packbf(w2, w3);
                    uint32_t l1 = packbf(w2 - bf_lo(h1), w3 - bf_hi(h1));
                    int cu = (c0 - 32) >> 1;
                    d_gbh[(size_t)grow*16 + cu    ] = h0;
                    d_gbl[(size_t)grow*16 + cu    ] = l0;
                    d_gbh[(size_t)grow*16 + cu + 1] = h1;
                    d_gbl[(size_t)grow*16 + cu + 1] = l1;
                }
            }
            __syncthreads();
            // f^T B-fragment writes: 512 uint2 entries per array
            #pragma unroll
            for (int j = 0; j < 2; j++) {
                int idx = t + 256*j;              // 0..511
                int key = idx >> 3, e = idx & 7;
                int ks = e >> 2, tq2 = e & 3;
                int cb = 16*ks + 2*tq2;
                const float* fr = s_f + key*33;
                float v0 = fr[cb], v1 = fr[cb+1], v8 = fr[cb+8], v9 = fr[cb+9];
                uint32_t hx = packbf(v0, v1);
                uint32_t hy = packbf(v8, v9);
                uint32_t lx = packbf(v0 - bf_lo(hx), v1 - bf_hi(hx));
                uint32_t ly = packbf(v8 - bf_lo(hy), v9 - bf_hi(hy));
                size_t dst = ((size_t)(bb*NN) + key0 + key)*8 + e;
                d_fqh[dst] = make_uint2(hx, hy);
                d_fql[dst] = make_uint2(lx, ly);
            }
        } else {
            __syncthreads();          // done reading ws; reuse as h staging
            float* sh = ws;                   // [64 keys][65] fp32
            #pragma unroll
            for (int rr = 0; rr < 4; rr++) {
                int lrow = r0 + rr;
                float v[4];
                unpk2(accA[rr], v[0], v[1]);
                unpk2(accB[rr], v[2], v[3]);
                #pragma unroll
                for (int q = 0; q < 4; q++) {
                    int c = c0 + q;
                    sh[lrow*65 + c] = v[q] + bh[(ph-1)*64 + c];
                }
            }
            __syncthreads();
            // h fp16 fragment-quad writes: 512 uint4 per phase (2/thread)
            #pragma unroll
            for (int j = 0; j < 2; j++) {
                int idx = t + 256*j;              // 0..511
                int K16loc = idx >> 7;            // 0..3
                int tqv    = (idx >> 5) & 3;
                int qv     = idx & 31;
                int k2 = K16loc*16 + 2*tqv;
                uint4 u;
                u.x = packf16(sh[k2*65+qv],        sh[(k2+1)*65+qv]);
                u.y = packf16(sh[(k2+8)*65+qv],    sh[(k2+9)*65+qv]);
                u.z = packf16(sh[k2*65+qv+32],     sh[(k2+1)*65+qv+32]);
                u.w = packf16(sh[(k2+8)*65+qv+32], sh[(k2+9)*65+qv+32]);
                size_t dst = ((size_t)(bb*256 + (key0>>4) + K16loc)*4 + tqv)*128
                           + (ph-1)*32 + qv;
                d_hf4[dst] = u;
            }
        }
    }
}

// ============================================================================
// Flash attention, fp16 PV with online row-max. Grid (32,4), 512 threads.
// Iter kb: QK(kb)->max/exp->P̃[kb&1],scale[kb&1]; PV(kb-1) lagging one tile.
// QK: bf16x2 3-term m16n8k16, warp = 16q x 32k (qg=w>>1, kg=w&1).
// PV: fp16 m16n8k16,          warp = 32q x 64c (mg=w>>2, ng=w&3).
// ============================================================================
#define FB_BYTES   6144                       // 64 keys x 96B
#define OFF_H_B    (4*FB_BYTES)               // 24576
#define H_STQ      130                        // uint4 stride per (K16,tq) row
#define H_TILE_B   (16*H_STQ*16)              // 33280
#define OFF_P_B    (OFF_H_B + 2*H_TILE_B)     // 91136
#define P_STRIDE   36                         // u32 per P row
#define P_BUF_B    (128*P_STRIDE*4)           // 18432
#define OFF_SC_B   (OFF_P_B + 2*P_BUF_B)      // 128000  scale_buf[2][128]
#define OFF_MX_B   (OFF_SC_B + 1024)          // 129024  sm_max[2][128]
#define OFF_PS_B   (OFF_MX_B + 1024)          // 130048  psum[2][128]
#define OFF_L_B    (OFF_PS_B + 1024)          // 131072  l[128]
#define ATT_SMEM_BYTES (OFF_L_B + 512)        // 131584

__device__ __forceinline__ void attn_load_f(uint32_t smb, int bb, int kb, int buf, int t) {
    int arr = t >> 8, rem = t & 255;
    int key = rem >> 2, ep = rem & 3;
    const uint2* src = (arr ? d_fql : d_fqh)
                     + ((size_t)(bb*NN + kb*64 + key))*8 + ep*2;
    cpa16(smb + (uint32_t)((buf*2+arr)*FB_BYTES + key*96 + ep*16), src);
}
__device__ __forceinline__ void attn_load_h(uint32_t smb, int bb, int kb, int buf, int t) {
    #pragma unroll
    for (int s = 0; s < 4; s++) {
        int idx = t + 512*s;                   // 0..2047
        int K16loc = idx >> 9, rem = idx & 511;
        int tqv = rem >> 7, q = rem & 127;
        const uint4* src = d_hf4 + ((size_t)(bb*256 + kb*4 + K16loc)*4 + tqv)*128 + q;
        cpa16(smb + (uint32_t)(OFF_H_B + buf*H_TILE_B + ((K16loc*4+tqv)*H_STQ + q)*16), src);
    }
}

__global__ __launch_bounds__(512, 1) void attn_kernel(
    const float* __restrict__ x, float* __restrict__ out)
{
    extern __shared__ char smraw[];
    const uint32_t smb = smem_u32(smraw);
    const int t    = threadIdx.x;
    const int w    = t >> 5, lane = t & 31;
    const int g    = lane >> 2, tq = lane & 3;
    const int bb   = blockIdx.y;
    const int q0   = blockIdx.x * BM;

    const int qg = w >> 1, kg = w & 1;    // QK: 8 qgroups x 2 kgroups
    const int mg = w >> 2, ng = w & 3;    // PV: 4 mgroups x 4 ngroups

    float* scbuf = (float*)(smraw + OFF_SC_B);
    float* smax  = (float*)(smraw + OFF_MX_B);
    float* psum  = (float*)(smraw + OFF_PS_B);
    float* lrow  = (float*)(smraw + OFF_L_B);
    if (t < 128) lrow[t] = 0.f;

    // hoisted QK A fragments (g bf16 hi/lo pairs)
    uint32_t ahi[2][4], alo[2][4];
    {
        const uint32_t* gbh = d_gbh + ((size_t)(bb*NN + q0 + qg*16))*16;
        const uint32_t* gbl = d_gbl + ((size_t)(bb*NN + q0 + qg*16))*16;
        #pragma unroll
        for (int ks = 0; ks < 2; ks++) {
            int cc = 8*ks + tq;
            ahi[ks][0] = gbh[g*16 + cc];
            ahi[ks][1] = gbh[(g+8)*16 + cc];
            ahi[ks][2] = gbh[g*16 + cc + 4];
            ahi[ks][3] = gbh[(g+8)*16 + cc + 4];
            alo[ks][0] = gbl[g*16 + cc];
            alo[ks][1] = gbl[(g+8)*16 + cc];
            alo[ks][2] = gbl[g*16 + cc + 4];
            alo[ks][3] = gbl[(g+8)*16 + cc + 4];
        }
    }

    float oacc[2][8][4];
    #pragma unroll
    for (int a=0;a<2;a++)
        #pragma unroll
        for (int b2=0;b2<8;b2++)
            #pragma unroll
            for (int c=0;c<4;c++) oacc[a][b2][c]=0.f;

    const float NEGINF = __int_as_float(0xff800000);
    float mold0 = NEGINF, mold1 = NEGINF;      // running row max (rows qg*16+g, +8)
    const int row0 = qg*16 + g;

    attn_load_f(smb, bb, 0, 0, t);
    cpa_commit();

    #pragma unroll 1
    for (int kb = 0; kb < NT; kb++) {
        const int pb = kb & 1;
        if (kb + 1 < NT) attn_load_f(smb, bb, kb+1, pb^1, t);
        cpa_commit();                          // group F(kb+1) (empty on last)
        attn_load_h(smb, bb, kb, pb, t);
        cpa_commit();                          // group H(kb)
        cpa_wait<2>();                         // F(kb), H(kb-1) complete
        __syncthreads();                       // publish f(kb), h(kb-1), P̃/scale(kb-1)

        // ---- QK(kb): S(16q x 32k per warp), bf16x2 3-term ----
        const uint2* fbh = (const uint2*)(smraw + (pb*2+0)*FB_BYTES);
        const uint2* fbl = (const uint2*)(smraw + (pb*2+1)*FB_BYTES);
        float sacc[4][4];
        #pragma unroll
        for (int nt=0;nt<4;nt++)
            #pragma unroll
            for (int c=0;c<4;c++) sacc[nt][c]=0.f;

        #pragma unroll
        for (int ks = 0; ks < 2; ks++) {
            #pragma unroll
            for (int nt = 0; nt < 4; nt++) {
                int key = kg*32 + nt*8 + g;
                uint2 qh = fbh[key*12 + ks*4 + tq];
                uint2 ql = fbl[key*12 + ks*4 + tq];
                mma16(sacc[nt], ahi[ks], ql.x, ql.y);
                mma16(sacc[nt], alo[ks], qh.x, qh.y);
                mma16(sacc[nt], ahi[ks], qh.x, qh.y);
            }
        }

        // ---- online row max across the kg pair ----
        float m0 = fmaxf(fmaxf(sacc[0][0], sacc[0][1]), fmaxf(sacc[1][0], sacc[1][1]));
        m0 = fmaxf(m0, fmaxf(fmaxf(sacc[2][0], sacc[2][1]), fmaxf(sacc[3][0], sacc[3][1])));
        float m1 = fmaxf(fmaxf(sacc[0][2], sacc[0][3]), fmaxf(sacc[1][2], sacc[1][3]));
        m1 = fmaxf(m1, fmaxf(fmaxf(sacc[2][2], sacc[2][3]), fmaxf(sacc[3][2], sacc[3][3])));
        m0 = fmaxf(m0, __shfl_xor_sync(0xffffffffu, m0, 1));
        m0 = fmaxf(m0, __shfl_xor_sync(0xffffffffu, m0, 2));
        m1 = fmaxf(m1, __shfl_xor_sync(0xffffffffu, m1, 1));
        m1 = fmaxf(m1, __shfl_xor_sync(0xffffffffu, m1, 2));
        if (tq == 0) {
            smax[kg*128 + row0    ] = m0;
            smax[kg*128 + row0 + 8] = m1;
        }
        barx(1 + qg, 64);
        float mnew0 = fmaxf(mold0, fmaxf(smax[row0    ], smax[128 + row0    ]));
        float mnew1 = fmaxf(mold1, fmaxf(smax[row0 + 8], smax[128 + row0 + 8]));
        float sc0 = __expf(mold0 - mnew0);     // exp(-inf)=0 on first tile
        float sc1 = __expf(mold1 - mnew1);
        mold0 = mnew0; mold1 = mnew1;
        if (kg == 0 && tq == 0) {
            scbuf[pb*128 + row0    ] = sc0;
            scbuf[pb*128 + row0 + 8] = sc1;
        }

        // ---- p̃ = exp(s - m), fp16 pack, store P̃[pb], partial sums ----
        {
            uint32_t* P = (uint32_t*)(smraw + OFF_P_B + pb*P_BUF_B);
            float rs0 = 0.f, rs1 = 0.f;
            #pragma unroll
            for (int nt = 0; nt < 4; nt++) {
                float p0 = __expf(sacc[nt][0] - mnew0);
                float p1 = __expf(sacc[nt][1] - mnew0);
                float p2 = __expf(sacc[nt][2] - mnew1);
                float p3 = __expf(sacc[nt][3] - mnew1);
                uint32_t u0 = packf16(p0, p1);
                uint32_t u1 = packf16(p2, p3);
                float2 f0 = __half22float2(*(const __half2*)&u0);
                float2 f1 = __half22float2(*(const __half2*)&u1);
                rs0 += f0.x + f0.y;
                rs1 += f1.x + f1.y;
                int cp = kg*16 + nt*4 + tq;
                P[(row0    )*P_STRIDE + cp] = u0;
                P[(row0 + 8)*P_STRIDE + cp] = u1;
            }
            rs0 += __shfl_xor_sync(0xffffffffu, rs0, 1);
            rs0 += __shfl_xor_sync(0xffffffffu, rs0, 2);
            rs1 += __shfl_xor_sync(0xffffffffu, rs1, 1);
            rs1 += __shfl_xor_sync(0xffffffffu, rs1, 2);
            if (tq == 0) {
                psum[kg*128 + row0    ] = rs0;
                psum[kg*128 + row0 + 8] = rs1;
            }
            barx(1 + qg, 64);
            if (kg == 0 && tq == 0) {
                lrow[row0    ] = lrow[row0    ]*sc0 + psum[row0    ] + psum[128 + row0    ];
                lrow[row0 + 8] = lrow[row0 + 8]*sc1 + psum[row0 + 8] + psum[128 + row0 + 8];
            }
        }

        // ---- PV(kb-1): oacc = oacc*scale(kb-1) + P̃(kb-1)·h(kb-1) ----
        if (kb > 0) {
            const uint32_t* Pp = (const uint32_t*)(smraw + OFF_P_B + (pb^1)*P_BUF_B);
            const uint4*    hq = (const uint4*)(smraw + OFF_H_B + (pb^1)*H_TILE_B);
            const float*   scb = scbuf + (pb^1)*128;
            float sc[2][2];
            #pragma unroll
            for (int mt = 0; mt < 2; mt++) {
                sc[mt][0] = scb[mg*32 + mt*16 + g    ];
                sc[mt][1] = scb[mg*32 + mt*16 + g + 8];
            }
            #pragma unroll
            for (int mt = 0; mt < 2; mt++)
                #pragma unroll
                for (int nt = 0; nt < 8; nt++) {
                    oacc[mt][nt][0] *= sc[mt][0];
                    oacc[mt][nt][1] *= sc[mt][0];
                    oacc[mt][nt][2] *= sc[mt][1];
                    oacc[mt][nt][3] *= sc[mt][1];
                }
            #pragma unroll
            for (int ks = 0; ks < 4; ks++) {
                uint32_t pa[2][4];
                #pragma unroll
                for (int mt = 0; mt < 2; mt++) {
                    int r = mg*32 + mt*16;
                    pa[mt][0] = Pp[(r+g  )*P_STRIDE + ks*8 + tq    ];
                    pa[mt][1] = Pp[(r+g+8)*P_STRIDE + ks*8 + tq    ];
                    pa[mt][2] = Pp[(r+g  )*P_STRIDE + ks*8 + tq + 4];
                    pa[mt][3] = Pp[(r+g+8)*P_STRIDE + ks*8 + tq + 4];
                }
                #pragma unroll
                for (int ntl = 0; ntl < 4; ntl++) {
                    uint4 u = hq[(ks*4 + tq)*H_STQ + ng*32 + ntl*8 + g];
                    mma16h(oacc[0][ntl],   pa[0], u.x, u.y);
                    mma16h(oacc[1][ntl],   pa[1], u.x, u.y);
                    mma16h(oacc[0][ntl+4], pa[0], u.z, u.w);
                    mma16h(oacc[1][ntl+4], pa[1], u.z, u.w);
                }
            }
        }

        __syncthreads();                       // protects P̃/scale/h/f reuse
    }

    // ---- final PV(NT-1) ----
    cpa_wait<0>();
    __syncthreads();
    {
        const int pb = (NT-1) & 1;
        const uint32_t* Pp = (const uint32_t*)(smraw + OFF_P_B + pb*P_BUF_B);
        const uint4*    hq = (const uint4*)(smraw + OFF_H_B + pb*H_TILE_B);
        const float*   scb = scbuf + pb*128;
        float sc[2][2];
        #pragma unroll
        for (int mt = 0; mt < 2; mt++) {
            sc[mt][0] = scb[mg*32 + mt*16 + g    ];
            sc[mt][1] = scb[mg*32 + mt*16 + g + 8];
        }
        #pragma unroll
        for (int mt = 0; mt < 2; mt++)
            #pragma unroll
            for (int nt = 0; nt < 8; nt++) {
                oacc[mt][nt][0] *= sc[mt][0];
                oacc[mt][nt][1] *= sc[mt][0];
                oacc[mt][nt][2] *= sc[mt][1];
                oacc[mt][nt][3] *= sc[mt][1];
            }
        #pragma unroll
        for (int ks = 0; ks < 4; ks++) {
            uint32_t pa[2][4];
            #pragma unroll
            for (int mt = 0; mt < 2; mt++) {
                int r = mg*32 + mt*16;
                pa[mt][0] = Pp[(r+g  )*P_STRIDE + ks*8 + tq    ];
                pa[mt][1] = Pp[(r+g+8)*P_STRIDE + ks*8 + tq    ];
                pa[mt][2] = Pp[(r+g  )*P_STRIDE + ks*8 + tq + 4];
                pa[mt][3] = Pp[(r+g+8)*P_STRIDE + ks*8 + tq + 4];
            }
            #pragma unroll
            for (int ntl = 0; ntl < 4; ntl++) {
                uint4 u = hq[(ks*4 + tq)*H_STQ + ng*32 + ntl*8 + g];
                mma16h(oacc[0][ntl],   pa[0], u.x, u.y);
                mma16h(oacc[1][ntl],   pa[1], u.x, u.y);
                mma16h(oacc[0][ntl+4], pa[0], u.z, u.w);
                mma16h(oacc[1][ntl+4], pa[1], u.z, u.w);
            }
        }
    }

    // ---- epilogue: out = x + O / l ----
    #pragma unroll
    for (int mt = 0; mt < 2; mt++) {
        int r0 = mg*32 + mt*16 + g;
        float inv0 = 1.0f / lrow[r0    ];
        float inv1 = 1.0f / lrow[r0 + 8];
        #pragma unroll
        for (int nt = 0; nt < 8; nt++) {
            int col = ng*64 + nt*8 + 2*tq;
            size_t base0 = ((size_t)(bb*NN + q0 + r0))*NC + col;
            size_t base1 = base0 + (size_t)8*NC;
            float2 xv0 = *(const float2*)(x + base0);
            float2 xv1 = *(const float2*)(x + base1);
            float2 o0, o1;
            o0.x = xv0.x + oacc[mt][nt][0]*inv0;
            o0.y = xv0.y + oacc[mt][nt][1]*inv0;
            o1.x = xv1.x + oacc[mt][nt][2]*inv1;
            o1.y = xv1.y + oacc[mt][nt][3]*inv1;
            *(float2*)(out + base0) = o0;
            *(float2*)(out + base1) = o1;
        }
    }
}

extern "C" void kernel_launch(void* const* d_in, const int* in_sizes, int n_in,
                              void* d_out, int out_size) {
    (void)in_sizes; (void)n_in; (void)out_size;
    const float* x  = (const float*)d_in[0];
    const float* Wf = (const float*)d_in[1];
    const float* bf = (const float*)d_in[2];
    const float* Wg = (const float*)d_in[3];
    const float* bg = (const float*)d_in[4];
    const float* Wh = (const float*)d_in[5];
    const float* bh = (const float*)d_in[6];
    float* out = (float*)d_out;

    cudaFuncSetAttribute(proj_kernel, cudaFuncAttributeMaxDynamicSharedMemorySize,
                         PROJ_SMEM_BYTES);
    cudaFuncSetAttribute(attn_kernel, cudaFuncAttributeMaxDynamicSharedMemorySize,
                         ATT_SMEM_BYTES);

    proj_kernel<<<(NB*NN)/64, 256, PROJ_SMEM_BYTES>>>(x, Wf, bf, Wg, bg, Wh, bh);

    dim3 grid(NN/BM, NB);
    attn_kernel<<<grid, 512, ATT_SMEM_BYTES>>>(x, out);
}